// round 1
// baseline (speedup 1.0000x reference)
#include <cuda_runtime.h>
#include <math.h>

#define DIM     1024
#define TLEN    16384
#define WIN     32
#define DH      64
#define HEADS   16
#define NWIN    (TLEN / WIN)      // 512
#define QKV_N   (3 * DIM)         // 3072

// ---------------- scratch (static device globals; no allocation) ----------------
static __device__ float g_normed[(size_t)TLEN * DIM];   // 64 MB, (T, C) row-major
static __device__ float g_qkv[(size_t)TLEN * QKV_N];    // 192 MB, (T, 3C) row-major
static __device__ float g_attn[(size_t)TLEN * DIM];     // 64 MB, (T, C) row-major

// =================================================================================
// Kernel 1: LayerNorm over channels + transpose (C,T) -> (T,C)
// block = (32,32); one block handles 32 tokens x all 1024 channels
// =================================================================================
__global__ void __launch_bounds__(1024) ln_transpose_kernel(
    const float* __restrict__ x,
    const float* __restrict__ gamma,
    const float* __restrict__ beta)
{
    __shared__ float reds[32][33];
    __shared__ float redq[32][33];
    __shared__ __align__(16) float tile[32][33];
    __shared__ float s_mean[32], s_rstd[32];

    const int tx = threadIdx.x;   // token within tile (coalesced dim on load)
    const int ty = threadIdx.y;   // channel within chunk
    const int t0 = blockIdx.x * 32;

    float sum = 0.f, sumsq = 0.f;
    #pragma unroll 4
    for (int c0 = 0; c0 < DIM; c0 += 32) {
        float v = x[(size_t)(c0 + ty) * TLEN + t0 + tx];
        sum += v;
        sumsq += v * v;
    }
    reds[ty][tx] = sum;
    redq[ty][tx] = sumsq;
    __syncthreads();
    for (int s = 16; s > 0; s >>= 1) {
        if (ty < s) {
            reds[ty][tx] += reds[ty + s][tx];
            redq[ty][tx] += redq[ty + s][tx];
        }
        __syncthreads();
    }
    if (ty == 0) {
        float m = reds[0][tx] * (1.0f / DIM);
        float var = redq[0][tx] * (1.0f / DIM) - m * m;
        s_mean[tx] = m;
        s_rstd[tx] = rsqrtf(var + 1e-5f);
    }
    __syncthreads();

    // pass 2: re-read (L2-hot), normalize, transpose through smem, write (T,C)
    for (int c0 = 0; c0 < DIM; c0 += 32) {
        float v = x[(size_t)(c0 + ty) * TLEN + t0 + tx];
        float nv = (v - s_mean[tx]) * s_rstd[tx] * gamma[c0 + ty] + beta[c0 + ty];
        tile[ty][tx] = nv;
        __syncthreads();
        // thread (tx,ty) writes channel c0+tx of token t0+ty
        g_normed[(size_t)(t0 + ty) * DIM + c0 + tx] = tile[tx][ty];
        __syncthreads();
    }
}

// =================================================================================
// Kernel 2: SGEMM-NT: C[M,N] = A[M,K] * B[N,K]^T   (A,B row-major, K contiguous)
// BM=BN=128, BK=16, 256 threads, 8x8 per thread. Optional residual add.
// =================================================================================
template <bool RESID>
__global__ void __launch_bounds__(256) sgemm_nt_kernel(
    const float* __restrict__ A,
    const float* __restrict__ B,
    float* __restrict__ C,
    const float* __restrict__ resid,
    int M, int N, int K)
{
    __shared__ __align__(16) float As[16][132];
    __shared__ __align__(16) float Bs[16][132];

    const int tid = threadIdx.x;
    const int m0 = blockIdx.y * 128;
    const int n0 = blockIdx.x * 128;
    const int ty = tid >> 4;        // 0..15
    const int tx = tid & 15;        // 0..15

    float acc[8][8];
    #pragma unroll
    for (int i = 0; i < 8; i++)
        #pragma unroll
        for (int j = 0; j < 8; j++) acc[i][j] = 0.f;

    for (int k0 = 0; k0 < K; k0 += 16) {
        // load 128x16 tiles of A and B (2 float4 per thread each), store transposed
        #pragma unroll
        for (int it = 0; it < 2; it++) {
            int idx = tid + it * 256;         // 0..511
            int r   = idx >> 2;               // 0..127
            int c4  = (idx & 3) << 2;         // 0,4,8,12
            float4 va = *(const float4*)&A[(size_t)(m0 + r) * K + k0 + c4];
            As[c4 + 0][r] = va.x; As[c4 + 1][r] = va.y;
            As[c4 + 2][r] = va.z; As[c4 + 3][r] = va.w;
            float4 vb = *(const float4*)&B[(size_t)(n0 + r) * K + k0 + c4];
            Bs[c4 + 0][r] = vb.x; Bs[c4 + 1][r] = vb.y;
            Bs[c4 + 2][r] = vb.z; Bs[c4 + 3][r] = vb.w;
        }
        __syncthreads();

        #pragma unroll
        for (int kk = 0; kk < 16; kk++) {
            float ra[8], rb[8];
            *(float4*)&ra[0] = *(const float4*)&As[kk][ty * 8];
            *(float4*)&ra[4] = *(const float4*)&As[kk][ty * 8 + 4];
            *(float4*)&rb[0] = *(const float4*)&Bs[kk][tx * 8];
            *(float4*)&rb[4] = *(const float4*)&Bs[kk][tx * 8 + 4];
            #pragma unroll
            for (int i = 0; i < 8; i++)
                #pragma unroll
                for (int j = 0; j < 8; j++)
                    acc[i][j] = fmaf(ra[i], rb[j], acc[i][j]);
        }
        __syncthreads();
    }

    // epilogue
    #pragma unroll
    for (int i = 0; i < 8; i++) {
        size_t crow = (size_t)(m0 + ty * 8 + i) * N + n0 + tx * 8;
        #pragma unroll
        for (int j4 = 0; j4 < 2; j4++) {
            float4 o;
            o.x = acc[i][j4 * 4 + 0];
            o.y = acc[i][j4 * 4 + 1];
            o.z = acc[i][j4 * 4 + 2];
            o.w = acc[i][j4 * 4 + 3];
            if (RESID) {
                float4 rv = *(const float4*)&resid[crow + j4 * 4];
                o.x += rv.x; o.y += rv.y; o.z += rv.z; o.w += rv.w;
            }
            *(float4*)&C[crow + j4 * 4] = o;
        }
    }
}

// =================================================================================
// Kernel 3: per (head, window) attention with RoPE. One block per (w, h).
// q,k,v are 32x64 slices of g_qkv. Non-causal softmax over the 32-token window.
// =================================================================================
__global__ void __launch_bounds__(256) attn_kernel()
{
    __shared__ __align__(16) float q[32][68];
    __shared__ __align__(16) float k[32][68];
    __shared__ __align__(16) float v[32][68];
    __shared__ float p[32][33];

    const int w = blockIdx.x;
    const int h = blockIdx.y;
    const int tid = threadIdx.x;

    const float* base = g_qkv + (size_t)w * WIN * QKV_N + h * DH;

    // load q,k,v tiles (32x64 each): 512 float4 per tensor / 256 threads
    #pragma unroll
    for (int it = 0; it < 2; it++) {
        int idx = tid + it * 256;       // 0..511
        int n   = idx >> 4;             // 0..31
        int d4  = (idx & 15) << 2;      // 0..60
        const float* rowp = base + (size_t)n * QKV_N + d4;
        *(float4*)&q[n][d4] = *(const float4*)(rowp);
        *(float4*)&k[n][d4] = *(const float4*)(rowp + DIM);
        *(float4*)&v[n][d4] = *(const float4*)(rowp + 2 * DIM);
    }
    __syncthreads();

    // RoPE on q,k: 32 positions x 32 pairs = 1024 pairs, 4 per thread
    #pragma unroll
    for (int it = 0; it < 4; it++) {
        int idx = tid + it * 256;       // 0..1023
        int n = idx >> 5;               // window position 0..31
        int i = idx & 31;               // pair index 0..31
        float invf = expf(-logf(10000.f) * (float)i * (1.0f / 32.0f));
        float ang  = (float)n * invf;
        float c = cosf(ang), s = sinf(ang);
        float qa = q[n][i], qb = q[n][i + 32];
        q[n][i]      = qa * c - qb * s;
        q[n][i + 32] = qb * c + qa * s;
        float ka = k[n][i], kb = k[n][i + 32];
        k[n][i]      = ka * c - kb * s;
        k[n][i + 32] = kb * c + ka * s;
    }
    __syncthreads();

    // S = scale * q k^T : each thread computes 4 entries of one row
    {
        int i  = tid >> 3;              // row 0..31
        int j0 = (tid & 7) << 2;        // 4 cols
        float s0 = 0.f, s1 = 0.f, s2 = 0.f, s3 = 0.f;
        #pragma unroll
        for (int d = 0; d < DH; d++) {
            float qv = q[i][d];
            s0 = fmaf(qv, k[j0 + 0][d], s0);
            s1 = fmaf(qv, k[j0 + 1][d], s1);
            s2 = fmaf(qv, k[j0 + 2][d], s2);
            s3 = fmaf(qv, k[j0 + 3][d], s3);
        }
        const float scale = 0.125f;     // 64^-0.5
        p[i][j0 + 0] = s0 * scale;
        p[i][j0 + 1] = s1 * scale;
        p[i][j0 + 2] = s2 * scale;
        p[i][j0 + 3] = s3 * scale;
    }
    __syncthreads();

    // softmax per row: 8 warps x 4 rows each, one column per lane
    {
        int warp = tid >> 5, lane = tid & 31;
        for (int r = warp; r < 32; r += 8) {
            float val = p[r][lane];
            float m = val;
            #pragma unroll
            for (int o = 16; o > 0; o >>= 1)
                m = fmaxf(m, __shfl_xor_sync(0xFFFFFFFFu, m, o));
            float e = expf(val - m);
            float sum = e;
            #pragma unroll
            for (int o = 16; o > 0; o >>= 1)
                sum += __shfl_xor_sync(0xFFFFFFFFu, sum, o);
            p[r][lane] = e / sum;
        }
    }
    __syncthreads();

    // O = P V : each thread computes 8 d's of one row
    {
        int oi = tid >> 3;              // row 0..31
        int d0 = (tid & 7) << 3;        // 8 cols
        float o[8];
        #pragma unroll
        for (int dd = 0; dd < 8; dd++) o[dd] = 0.f;
        #pragma unroll
        for (int j = 0; j < 32; j++) {
            float pv = p[oi][j];
            #pragma unroll
            for (int dd = 0; dd < 8; dd++)
                o[dd] = fmaf(pv, v[j][d0 + dd], o[dd]);
        }
        float* outp = g_attn + (size_t)(w * WIN + oi) * DIM + h * DH + d0;
        float4 o0, o1;
        o0.x = o[0]; o0.y = o[1]; o0.z = o[2]; o0.w = o[3];
        o1.x = o[4]; o1.y = o[5]; o1.z = o[6]; o1.w = o[7];
        *(float4*)(outp)     = o0;
        *(float4*)(outp + 4) = o1;
    }
}

// =================================================================================
// launch
// =================================================================================
extern "C" void kernel_launch(void* const* d_in, const int* in_sizes, int n_in,
                              void* d_out, int out_size)
{
    (void)in_sizes; (void)n_in; (void)out_size;
    const float* x     = (const float*)d_in[0];
    const float* w_qkv = (const float*)d_in[1];
    const float* w_out = (const float*)d_in[2];
    const float* gamma = (const float*)d_in[3];
    const float* beta  = (const float*)d_in[4];
    float* out = (float*)d_out;

    float *normed, *qkv, *attn;
    cudaGetSymbolAddress((void**)&normed, g_normed);
    cudaGetSymbolAddress((void**)&qkv,    g_qkv);
    cudaGetSymbolAddress((void**)&attn,   g_attn);

    // 1) LayerNorm + transpose -> g_normed (T, C)
    ln_transpose_kernel<<<TLEN / 32, dim3(32, 32)>>>(x, gamma, beta);

    // 2) QKV GEMM: (T,3C) = normed (T,C) @ w_qkv^T
    sgemm_nt_kernel<false><<<dim3(QKV_N / 128, TLEN / 128), 256>>>(
        normed, w_qkv, qkv, nullptr, TLEN, QKV_N, DIM);

    // 3) windowed RoPE attention -> g_attn (T, C)
    attn_kernel<<<dim3(NWIN, HEADS), 256>>>();

    // 4) out = (w_out @ attn^T) + x, written directly as (C, T)
    sgemm_nt_kernel<true><<<dim3(TLEN / 128, DIM / 128), 256>>>(
        w_out, attn, out, x, DIM, TLEN, DIM);
}

// round 3
// speedup vs baseline: 2.5272x; 2.5272x over previous
#include <cuda_runtime.h>
#include <math.h>
#include <stdint.h>

#define DIM     1024
#define TLEN    16384
#define WIN     32
#define DH      64
#define HEADS   16
#define NWIN    (TLEN / WIN)      // 512
#define QKV_N   (3 * DIM)         // 3072

// ---------------- scratch (static device globals; no allocation) ----------------
static __device__ float g_normed[(size_t)TLEN * DIM];    // (T, C) tf32-rounded
static __device__ float g_qkv[(size_t)TLEN * QKV_N];     // (T, 3C) fp32
static __device__ float g_attn[(size_t)TLEN * DIM];      // (T, C) tf32-rounded
static __device__ float g_wqkv_r[(size_t)QKV_N * DIM];   // tf32-rounded weights
static __device__ float g_wout_r[(size_t)DIM * DIM];     // tf32-rounded weights

// =============================== helpers ===================================
__device__ __forceinline__ uint32_t smem_u32(const void* p) {
    uint32_t a;
    asm("{ .reg .u64 t; cvta.to.shared.u64 t, %1; cvt.u32.u64 %0, t; }" : "=r"(a) : "l"(p));
    return a;
}
__device__ __forceinline__ float rna_tf32(float x) {
    uint32_t r;
    asm("cvt.rna.tf32.f32 %0, %1;" : "=r"(r) : "f"(x));
    return __uint_as_float(r);
}

// =================================================================================
// Kernel 0: round fp32 -> tf32 representable (removes HW-truncation bias)
// =================================================================================
__global__ void round_tf32_kernel(const float* __restrict__ in, float* __restrict__ out, int n4)
{
    int i = blockIdx.x * blockDim.x + threadIdx.x;
    if (i < n4) {
        float4 v = *(const float4*)&in[i * 4];
        v.x = rna_tf32(v.x); v.y = rna_tf32(v.y);
        v.z = rna_tf32(v.z); v.w = rna_tf32(v.w);
        *(float4*)&out[i * 4] = v;
    }
}

// =================================================================================
// Kernel 1: LayerNorm over channels + transpose (C,T) -> (T,C), tf32-rounded output
// =================================================================================
__global__ void __launch_bounds__(1024) ln_transpose_kernel(
    const float* __restrict__ x,
    const float* __restrict__ gamma,
    const float* __restrict__ beta)
{
    __shared__ float reds[32][33];
    __shared__ float redq[32][33];
    __shared__ __align__(16) float tile[32][33];
    __shared__ float s_mean[32], s_rstd[32];

    const int tx = threadIdx.x;
    const int ty = threadIdx.y;
    const int t0 = blockIdx.x * 32;

    float sum = 0.f, sumsq = 0.f;
    #pragma unroll 4
    for (int c0 = 0; c0 < DIM; c0 += 32) {
        float v = x[(size_t)(c0 + ty) * TLEN + t0 + tx];
        sum += v;
        sumsq += v * v;
    }
    reds[ty][tx] = sum;
    redq[ty][tx] = sumsq;
    __syncthreads();
    for (int s = 16; s > 0; s >>= 1) {
        if (ty < s) {
            reds[ty][tx] += reds[ty + s][tx];
            redq[ty][tx] += redq[ty + s][tx];
        }
        __syncthreads();
    }
    if (ty == 0) {
        float m = reds[0][tx] * (1.0f / DIM);
        float var = redq[0][tx] * (1.0f / DIM) - m * m;
        s_mean[tx] = m;
        s_rstd[tx] = rsqrtf(var + 1e-5f);
    }
    __syncthreads();

    for (int c0 = 0; c0 < DIM; c0 += 32) {
        float v = x[(size_t)(c0 + ty) * TLEN + t0 + tx];
        float nv = (v - s_mean[tx]) * s_rstd[tx] * gamma[c0 + ty] + beta[c0 + ty];
        tile[ty][tx] = nv;
        __syncthreads();
        g_normed[(size_t)(t0 + ty) * DIM + c0 + tx] = rna_tf32(tile[tx][ty]);
        __syncthreads();
    }
}

// =================================================================================
// Kernel 2: mma.sync tf32 GEMM-NT: C[M,N] = A[M,K] * B[N,K]^T   (+resid)
// BM=BN=128, BK=32, 3-stage cp.async pipeline, 256 threads (8 warps, 64x32 each).
// Smem rows padded to 36 floats -> conflict-free fragment LDS.
// =================================================================================
#define GBM 128
#define GBN 128
#define GBK 32
#define GSTAGES 3
#define ROWF 36
#define TILEF (128 * ROWF)
#define STAGEF (2 * TILEF)
#define GSMEM_BYTES (GSTAGES * STAGEF * 4)   // 110592 B

template <bool RESID>
__global__ void __launch_bounds__(256) mma_gemm_nt(
    const float* __restrict__ A,
    const float* __restrict__ B,
    float* __restrict__ C,
    const float* __restrict__ resid,
    int M, int N, int K)
{
    extern __shared__ float sm[];
    const int tid  = threadIdx.x;
    const int wid  = tid >> 5;
    const int lane = tid & 31;
    const int g = lane >> 2;          // 0..7
    const int t = lane & 3;           // 0..3
    const int m0 = blockIdx.y * GBM;
    const int n0 = blockIdx.x * GBN;
    const int wm = (wid >> 2) * 64;   // warp m offset within block
    const int wn = (wid & 3) * 32;    // warp n offset within block
    const int KC = K / GBK;

    float c[4][4][4];
    #pragma unroll
    for (int mi = 0; mi < 4; mi++)
        #pragma unroll
        for (int ni = 0; ni < 4; ni++)
            #pragma unroll
            for (int j = 0; j < 4; j++) c[mi][ni][j] = 0.f;

    // per-thread load coordinates (4 16B chunks per tile)
    // chunk idx = tid + i*256; row = idx>>3; c4 = (idx&7)*4 floats
    // prologue: stages 0 and 1
    #pragma unroll
    for (int s = 0; s < GSTAGES - 1; s++) {
        float* as = sm + s * STAGEF;
        float* bs = as + TILEF;
        #pragma unroll
        for (int i = 0; i < 4; i++) {
            int idx = tid + i * 256;
            int row = idx >> 3;
            int c4  = (idx & 7) << 2;
            uint32_t sa = smem_u32(as + row * ROWF + c4);
            const float* ga = A + (size_t)(m0 + row) * K + s * GBK + c4;
            asm volatile("cp.async.cg.shared.global [%0], [%1], 16;" :: "r"(sa), "l"(ga));
            uint32_t sb = smem_u32(bs + row * ROWF + c4);
            const float* gb = B + (size_t)(n0 + row) * K + s * GBK + c4;
            asm volatile("cp.async.cg.shared.global [%0], [%1], 16;" :: "r"(sb), "l"(gb));
        }
        asm volatile("cp.async.commit_group;");
    }

    for (int kc = 0; kc < KC; kc++) {
        if (kc + 1 < KC) asm volatile("cp.async.wait_group 1;");
        else             asm volatile("cp.async.wait_group 0;");
        __syncthreads();

        // issue loads for stage kc+2 (slot reused from compute of iter kc-1, done by all)
        int nxt = kc + 2;
        if (nxt < KC) {
            int slot = nxt % GSTAGES;
            float* as = sm + slot * STAGEF;
            float* bs = as + TILEF;
            #pragma unroll
            for (int i = 0; i < 4; i++) {
                int idx = tid + i * 256;
                int row = idx >> 3;
                int c4  = (idx & 7) << 2;
                uint32_t sa = smem_u32(as + row * ROWF + c4);
                const float* ga = A + (size_t)(m0 + row) * K + nxt * GBK + c4;
                asm volatile("cp.async.cg.shared.global [%0], [%1], 16;" :: "r"(sa), "l"(ga));
                uint32_t sb = smem_u32(bs + row * ROWF + c4);
                const float* gb = B + (size_t)(n0 + row) * K + nxt * GBK + c4;
                asm volatile("cp.async.cg.shared.global [%0], [%1], 16;" :: "r"(sb), "l"(gb));
            }
            asm volatile("cp.async.commit_group;");
        }

        const float* as = sm + (kc % GSTAGES) * STAGEF;
        const float* bs = as + TILEF;

        #pragma unroll
        for (int kk = 0; kk < GBK; kk += 8) {
            uint32_t a[4][4], b[4][2];
            #pragma unroll
            for (int mi = 0; mi < 4; mi++) {
                const float* ap = as + (wm + mi * 16 + g) * ROWF + kk + t;
                a[mi][0] = __float_as_uint(ap[0]);
                a[mi][1] = __float_as_uint(ap[8 * ROWF]);
                a[mi][2] = __float_as_uint(ap[4]);
                a[mi][3] = __float_as_uint(ap[8 * ROWF + 4]);
            }
            #pragma unroll
            for (int ni = 0; ni < 4; ni++) {
                const float* bp = bs + (wn + ni * 8 + g) * ROWF + kk + t;
                b[ni][0] = __float_as_uint(bp[0]);
                b[ni][1] = __float_as_uint(bp[4]);
            }
            #pragma unroll
            for (int mi = 0; mi < 4; mi++)
                #pragma unroll
                for (int ni = 0; ni < 4; ni++)
                    asm volatile(
                        "mma.sync.aligned.m16n8k8.row.col.f32.tf32.tf32.f32 "
                        "{%0,%1,%2,%3},{%4,%5,%6,%7},{%8,%9},{%0,%1,%2,%3};"
                        : "+f"(c[mi][ni][0]), "+f"(c[mi][ni][1]),
                          "+f"(c[mi][ni][2]), "+f"(c[mi][ni][3])
                        : "r"(a[mi][0]), "r"(a[mi][1]), "r"(a[mi][2]), "r"(a[mi][3]),
                          "r"(b[ni][0]), "r"(b[ni][1]));
        }
    }

    // epilogue: thread (g,t) owns rows (wm+16mi+g, +8), cols (wn+8ni+2t, +1)
    #pragma unroll
    for (int mi = 0; mi < 4; mi++) {
        #pragma unroll
        for (int ni = 0; ni < 4; ni++) {
            size_t r0  = (size_t)(m0 + wm + mi * 16 + g);
            size_t col = (size_t)(n0 + wn + ni * 8 + 2 * t);
            size_t off0 = r0 * N + col;
            size_t off1 = (r0 + 8) * N + col;
            float2 v0 = make_float2(c[mi][ni][0], c[mi][ni][1]);
            float2 v1 = make_float2(c[mi][ni][2], c[mi][ni][3]);
            if (RESID) {
                float2 rv0 = *(const float2*)&resid[off0];
                float2 rv1 = *(const float2*)&resid[off1];
                v0.x += rv0.x; v0.y += rv0.y;
                v1.x += rv1.x; v1.y += rv1.y;
            }
            *(float2*)&C[off0] = v0;
            *(float2*)&C[off1] = v1;
        }
    }
}

// =================================================================================
// Kernel 3: per (head, window) attention with RoPE (fp32), tf32-rounded output
// =================================================================================
__global__ void __launch_bounds__(256) attn_kernel()
{
    __shared__ __align__(16) float q[32][68];
    __shared__ __align__(16) float k[32][68];
    __shared__ __align__(16) float v[32][68];
    __shared__ float p[32][33];

    const int w = blockIdx.x;
    const int h = blockIdx.y;
    const int tid = threadIdx.x;

    const float* base = g_qkv + (size_t)w * WIN * QKV_N + h * DH;

    #pragma unroll
    for (int it = 0; it < 2; it++) {
        int idx = tid + it * 256;
        int n   = idx >> 4;
        int d4  = (idx & 15) << 2;
        const float* rowp = base + (size_t)n * QKV_N + d4;
        *(float4*)&q[n][d4] = *(const float4*)(rowp);
        *(float4*)&k[n][d4] = *(const float4*)(rowp + DIM);
        *(float4*)&v[n][d4] = *(const float4*)(rowp + 2 * DIM);
    }
    __syncthreads();

    #pragma unroll
    for (int it = 0; it < 4; it++) {
        int idx = tid + it * 256;
        int n = idx >> 5;
        int i = idx & 31;
        float invf = expf(-logf(10000.f) * (float)i * (1.0f / 32.0f));
        float ang  = (float)n * invf;
        float c = cosf(ang), s = sinf(ang);
        float qa = q[n][i], qb = q[n][i + 32];
        q[n][i]      = qa * c - qb * s;
        q[n][i + 32] = qb * c + qa * s;
        float ka = k[n][i], kb = k[n][i + 32];
        k[n][i]      = ka * c - kb * s;
        k[n][i + 32] = kb * c + ka * s;
    }
    __syncthreads();

    {
        int i  = tid >> 3;
        int j0 = (tid & 7) << 2;
        float s0 = 0.f, s1 = 0.f, s2 = 0.f, s3 = 0.f;
        #pragma unroll
        for (int d = 0; d < DH; d++) {
            float qv = q[i][d];
            s0 = fmaf(qv, k[j0 + 0][d], s0);
            s1 = fmaf(qv, k[j0 + 1][d], s1);
            s2 = fmaf(qv, k[j0 + 2][d], s2);
            s3 = fmaf(qv, k[j0 + 3][d], s3);
        }
        const float scale = 0.125f;
        p[i][j0 + 0] = s0 * scale;
        p[i][j0 + 1] = s1 * scale;
        p[i][j0 + 2] = s2 * scale;
        p[i][j0 + 3] = s3 * scale;
    }
    __syncthreads();

    {
        int warp = tid >> 5, lane = tid & 31;
        for (int r = warp; r < 32; r += 8) {
            float val = p[r][lane];
            float m = val;
            #pragma unroll
            for (int o = 16; o > 0; o >>= 1)
                m = fmaxf(m, __shfl_xor_sync(0xFFFFFFFFu, m, o));
            float e = expf(val - m);
            float sum = e;
            #pragma unroll
            for (int o = 16; o > 0; o >>= 1)
                sum += __shfl_xor_sync(0xFFFFFFFFu, sum, o);
            p[r][lane] = e / sum;
        }
    }
    __syncthreads();

    {
        int oi = tid >> 3;
        int d0 = (tid & 7) << 3;
        float o[8];
        #pragma unroll
        for (int dd = 0; dd < 8; dd++) o[dd] = 0.f;
        #pragma unroll
        for (int j = 0; j < 32; j++) {
            float pv = p[oi][j];
            #pragma unroll
            for (int dd = 0; dd < 8; dd++)
                o[dd] = fmaf(pv, v[j][d0 + dd], o[dd]);
        }
        float* outp = g_attn + (size_t)(w * WIN + oi) * DIM + h * DH + d0;
        float4 o0, o1;
        o0.x = rna_tf32(o[0]); o0.y = rna_tf32(o[1]);
        o0.z = rna_tf32(o[2]); o0.w = rna_tf32(o[3]);
        o1.x = rna_tf32(o[4]); o1.y = rna_tf32(o[5]);
        o1.z = rna_tf32(o[6]); o1.w = rna_tf32(o[7]);
        *(float4*)(outp)     = o0;
        *(float4*)(outp + 4) = o1;
    }
}

// =================================================================================
// launch
// =================================================================================
extern "C" void kernel_launch(void* const* d_in, const int* in_sizes, int n_in,
                              void* d_out, int out_size)
{
    (void)in_sizes; (void)n_in; (void)out_size;
    const float* x     = (const float*)d_in[0];
    const float* w_qkv = (const float*)d_in[1];
    const float* w_out = (const float*)d_in[2];
    const float* gamma = (const float*)d_in[3];
    const float* beta  = (const float*)d_in[4];
    float* out = (float*)d_out;

    float *normed, *qkv, *attn, *wqkv_r, *wout_r;
    cudaGetSymbolAddress((void**)&normed, g_normed);
    cudaGetSymbolAddress((void**)&qkv,    g_qkv);
    cudaGetSymbolAddress((void**)&attn,   g_attn);
    cudaGetSymbolAddress((void**)&wqkv_r, g_wqkv_r);
    cudaGetSymbolAddress((void**)&wout_r, g_wout_r);

    cudaFuncSetAttribute(mma_gemm_nt<false>, cudaFuncAttributeMaxDynamicSharedMemorySize, GSMEM_BYTES);
    cudaFuncSetAttribute(mma_gemm_nt<true>,  cudaFuncAttributeMaxDynamicSharedMemorySize, GSMEM_BYTES);

    // 0) round weights to tf32-representable
    round_tf32_kernel<<<(QKV_N * DIM / 4 + 255) / 256, 256>>>(w_qkv, wqkv_r, QKV_N * DIM / 4);
    round_tf32_kernel<<<(DIM * DIM / 4 + 255) / 256, 256>>>(w_out, wout_r, DIM * DIM / 4);

    // 1) LayerNorm + transpose -> g_normed (T, C), tf32-rounded
    ln_transpose_kernel<<<TLEN / 32, dim3(32, 32)>>>(x, gamma, beta);

    // 2) QKV GEMM (tf32 mma.sync): (T,3C) = normed @ w_qkv^T
    mma_gemm_nt<false><<<dim3(QKV_N / GBN, TLEN / GBM), 256, GSMEM_BYTES>>>(
        normed, wqkv_r, qkv, nullptr, TLEN, QKV_N, DIM);

    // 3) windowed RoPE attention -> g_attn (T, C), tf32-rounded
    attn_kernel<<<dim3(NWIN, HEADS), 256>>>();

    // 4) out = (w_out @ attn^T) + x, written directly as (C, T)
    mma_gemm_nt<true><<<dim3(TLEN / GBN, DIM / GBM), 256, GSMEM_BYTES>>>(
        wout_r, attn, out, x, DIM, TLEN, DIM);
}